// round 17
// baseline (speedup 1.0000x reference)
#include <cuda_runtime.h>
#include <cuda_fp16.h>
#include <cstdint>

#define NB 16
#define LA 1024
#define LB 1024
#define HD 512
#define EPSV 1e-13f

__device__ float  g_S [(long long)NB * LA * LB];
__device__ __half g_P [(long long)NB * LA * LB];    // row-softmax out (fp16, normalized)
__device__ __half g_QH[(long long)NB * LA * LB];    // col-softmax out hi (UNNORMALIZED)
__device__ __half g_QL[(long long)NB * LA * LB];    // col-softmax out lo (UNNORMALIZED)
__device__ float  g_scQ[(long long)NB * LB];        // per-column scale for Q
__device__ __half g_pmH[(long long)NB * LA * HD];
__device__ __half g_pmL[(long long)NB * LA * HD];
__device__ __half g_hyH[(long long)NB * LB * HD];
__device__ __half g_hyL[(long long)NB * LB * HD];
__device__ int    g_cnt1[NB];                       // G1 CTAs done per batch
__device__ int    g_cnt2[NB];                       // softmax blocks done per batch

#define N_G1   (8 * 8 * NB)                 // 1024
#define N_SM   ((LA + LB / 32) * NB)        // 16896
#define SM_PER_B (LA + LB / 32)             // 1056
#define N_G23  (4 * 8 * 2 * NB)             // 1024

// ---------------------------------------------------------------------------
__device__ __forceinline__ uint32_t smem_u32(const void* p) {
    uint32_t a;
    asm("{ .reg .u64 t; cvta.to.shared.u64 t, %1; cvt.u32.u64 %0, t; }" : "=r"(a) : "l"(p));
    return a;
}
__device__ __forceinline__ uint32_t swzMN(uint32_t off) { return off ^ ((off >> 4) & 0x70); }
__device__ __forceinline__ uint32_t swzK(uint32_t off)  { return off ^ (((off >> 7) & 0x3) << 4); }

__device__ __forceinline__ void cp16(uint32_t dst, const void* src) {
    asm volatile("cp.async.cg.shared.global [%0], [%1], 16;"
                 :: "r"(dst), "l"(src) : "memory");
}
__device__ __forceinline__ void cp_commit() {
    asm volatile("cp.async.commit_group;" ::: "memory");
}
__device__ __forceinline__ void cp_wait1()  {
    asm volatile("cp.async.wait_group 1;" ::: "memory");
}

// GPU-scope release increment / acquire load
__device__ __forceinline__ void red_release_add1(int* p) {
    asm volatile("red.release.gpu.global.add.s32 [%0], 1;" :: "l"(p) : "memory");
}
__device__ __forceinline__ int ld_acquire(const int* p) {
    int v;
    asm volatile("ld.acquire.gpu.global.s32 %0, [%1];" : "=r"(v) : "l"(p) : "memory");
    return v;
}

__device__ __forceinline__ void ldsm4(uint32_t* r, uint32_t addr) {
    asm volatile("ldmatrix.sync.aligned.m8n8.x4.shared.b16 {%0,%1,%2,%3}, [%4];"
                 : "=r"(r[0]), "=r"(r[1]), "=r"(r[2]), "=r"(r[3]) : "r"(addr));
}
__device__ __forceinline__ void ldsm4t(uint32_t* r, uint32_t addr) {
    asm volatile("ldmatrix.sync.aligned.m8n8.x4.trans.shared.b16 {%0,%1,%2,%3}, [%4];"
                 : "=r"(r[0]), "=r"(r[1]), "=r"(r[2]), "=r"(r[3]) : "r"(addr));
}
__device__ __forceinline__ void mma_f16(float* c, const uint32_t* a, uint32_t b0, uint32_t b1) {
    asm volatile("mma.sync.aligned.m16n8k16.row.col.f32.f16.f16.f32 "
                 "{%0,%1,%2,%3}, {%4,%5,%6,%7}, {%8,%9}, {%0,%1,%2,%3};"
                 : "+f"(c[0]), "+f"(c[1]), "+f"(c[2]), "+f"(c[3])
                 : "r"(a[0]), "r"(a[1]), "r"(a[2]), "r"(a[3]), "r"(b0), "r"(b1));
}
__device__ __forceinline__ void mma_f16h(uint32_t* c, const uint32_t* a, uint32_t b0, uint32_t b1) {
    asm volatile("mma.sync.aligned.m16n8k16.row.col.f16.f16.f16.f16 "
                 "{%0,%1}, {%2,%3,%4,%5}, {%6,%7}, {%0,%1};"
                 : "+r"(c[0]), "+r"(c[1])
                 : "r"(a[0]), "r"(a[1]), "r"(a[2]), "r"(a[3]), "r"(b0), "r"(b1));
}

// ---------------------------------------------------------------------------
__global__ __launch_bounds__(256)
void split_kernel(const float* __restrict__ src, __half* __restrict__ oh,
                  __half* __restrict__ ol)
{
    long long i = ((long long)blockIdx.x * 256 + threadIdx.x) * 4;
    float4 v = *(const float4*)(src + i);
    __half h0 = __float2half_rn(v.x), h1 = __float2half_rn(v.y);
    __half h2 = __float2half_rn(v.z), h3 = __float2half_rn(v.w);
    __half l0 = __float2half_rn(v.x - __half2float(h0));
    __half l1 = __float2half_rn(v.y - __half2float(h1));
    __half l2 = __float2half_rn(v.z - __half2float(h2));
    __half l3 = __float2half_rn(v.w - __half2float(h3));
    __half2 ha = __halves2half2(h0, h1), hb = __halves2half2(h2, h3);
    __half2 la = __halves2half2(l0, l1), lb = __halves2half2(l2, l3);
    *(uint2*)(oh + i) = make_uint2(*(uint32_t*)&ha, *(uint32_t*)&hb);
    *(uint2*)(ol + i) = make_uint2(*(uint32_t*)&la, *(uint32_t*)&lb);
}

// ---------------------------------------------------------------------------
__device__ __forceinline__ void load_opK(const __half* __restrict__ src, int ld,
                                         int x0, int k0, uint32_t dstb, int tid) {
#pragma unroll
    for (int it = 0; it < 2; it++) {
        int u = it * 256 + tid;
        int x = u >> 2, c = u & 3;
        cp16(dstb + swzK((uint32_t)(x * 64 + c * 16)),
             src + (long long)(x0 + x) * ld + k0 + c * 8);
    }
}
__device__ __forceinline__ void load_opMN(const __half* __restrict__ src, int ld,
                                          int x0, int k0, uint32_t dstb, int tid) {
#pragma unroll
    for (int it = 0; it < 2; it++) {
        int u = it * 256 + tid;
        int k = u >> 4, c = u & 15;
        cp16(dstb + swzMN((uint32_t)(k * 256 + c * 16)),
             src + (long long)(k0 + k) * ld + x0 + c * 8);
    }
}

#define OPQ 8192

// ---------------------------------------------------------------------------
// fp32-acc GEMM body (CHAINS = 1 or 3), optional per-output-row scale.
// ---------------------------------------------------------------------------
template <int CHAINS>
__device__ __forceinline__ void gemm_body(
    const __half* pAH, const __half* pAL,
    const __half* pBH, const __half* pBL,
    float* C, int K, int lda, int ldb, int ldc,
    int m0, int n0, int amode, int bmode,
    const float* rowscale,
    uint32_t sb, int tid, int wid, int lane)
{
    constexpr uint32_t STAGEB = (CHAINS == 3) ? 4 * OPQ : 2 * OPQ;
    constexpr uint32_t BOFF   = (CHAINS == 3) ? 2 * OPQ : OPQ;
    const int wm = wid >> 1, wn = wid & 1;
    const int NKT = K >> 5;

    float acc[2][8][4];
#pragma unroll
    for (int t = 0; t < 2; t++)
#pragma unroll
        for (int q = 0; q < 8; q++)
#pragma unroll
            for (int e = 0; e < 4; e++) acc[t][q][e] = 0.f;

    auto load_stage = [&](int kt, int st) {
        uint32_t nb = sb + (uint32_t)st * STAGEB;
        int k0 = kt * 32;
        if (amode == 0) {
            load_opK(pAH, lda, m0, k0, nb, tid);
            if (CHAINS == 3) load_opK(pAL, lda, m0, k0, nb + OPQ, tid);
        } else {
            load_opMN(pAH, lda, m0, k0, nb, tid);
            if (CHAINS == 3) load_opMN(pAL, lda, m0, k0, nb + OPQ, tid);
        }
        if (bmode == 0) {
            load_opK(pBH, ldb, n0, k0, nb + BOFF, tid);
            if (CHAINS == 3) load_opK(pBL, ldb, n0, k0, nb + BOFF + OPQ, tid);
        } else {
            load_opMN(pBH, ldb, n0, k0, nb + BOFF, tid);
            if (CHAINS == 3) load_opMN(pBL, ldb, n0, k0, nb + BOFF + OPQ, tid);
        }
        cp_commit();
    };

    load_stage(0, 0);
    load_stage(1, 1);

    int st = 0;
    for (int kt = 0; kt < NKT; kt++) {
        cp_wait1();
        __syncthreads();
        if (kt + 2 < NKT) load_stage(kt + 2, (st + 2) % 3);

        const uint32_t tb = sb + (uint32_t)st * STAGEB;
        const uint32_t sAh = tb, sAl = tb + OPQ;
        const uint32_t sBh = tb + BOFF, sBl = tb + BOFF + OPQ;
#pragma unroll
        for (int ks = 0; ks < 2; ks++) {
            uint32_t a_hi[2][4], a_lo[2][4];
#pragma unroll
            for (int t = 0; t < 2; t++) {
                if (amode == 0) {
                    uint32_t off = (uint32_t)((wm * 32 + t * 16 + (lane & 15)) * 64
                                              + ks * 32 + (lane >> 4) * 16);
                    uint32_t sw = swzK(off);
                    ldsm4(a_hi[t], sAh + sw);
                    if (CHAINS == 3) ldsm4(a_lo[t], sAl + sw);
                } else {
                    uint32_t off = (uint32_t)((ks * 16 + (lane & 7) + ((lane >> 4) & 1) * 8) * 256
                                              + (wm * 32 + t * 16 + ((lane >> 3) & 1) * 8) * 2);
                    uint32_t sw = swzMN(off);
                    ldsm4t(a_hi[t], sAh + sw);
                    if (CHAINS == 3) ldsm4t(a_lo[t], sAl + sw);
                }
            }
#pragma unroll
            for (int p = 0; p < 4; p++) {
                uint32_t b_hi[4], b_lo[4];
                if (bmode == 0) {
                    uint32_t off = (uint32_t)((wn * 64 + p * 16 + (lane & 7) + ((lane >> 4) << 3)) * 64
                                              + ks * 32 + ((lane >> 3) & 1) * 16);
                    uint32_t sw = swzK(off);
                    ldsm4(b_hi, sBh + sw);
                    if (CHAINS == 3) ldsm4(b_lo, sBl + sw);
                } else {
                    uint32_t off = (uint32_t)((ks * 16 + (lane & 15)) * 256
                                              + (wn * 64 + p * 16 + (lane >> 4) * 8) * 2);
                    uint32_t sw = swzMN(off);
                    ldsm4t(b_hi, sBh + sw);
                    if (CHAINS == 3) ldsm4t(b_lo, sBl + sw);
                }
#pragma unroll
                for (int t = 0; t < 2; t++)
#pragma unroll
                    for (int qq = 0; qq < 2; qq++) {
                        const int q = p * 2 + qq, h = qq * 2;
                        mma_f16(acc[t][q], a_hi[t], b_hi[h], b_hi[h + 1]);
                        if (CHAINS == 3) {
                            mma_f16(acc[t][q], a_hi[t], b_lo[h], b_lo[h + 1]);
                            mma_f16(acc[t][q], a_lo[t], b_hi[h], b_hi[h + 1]);
                        }
                    }
            }
        }
        st = (st + 1) % 3;
    }

    const int row0 = lane >> 2, col0 = (lane & 3) * 2;
#pragma unroll
    for (int t = 0; t < 2; t++) {
        const int r = m0 + wm * 32 + t * 16 + row0;
        float s0 = 1.f, s1 = 1.f;
        if (rowscale) { s0 = rowscale[r]; s1 = rowscale[r + 8]; }
#pragma unroll
        for (int q = 0; q < 8; q++) {
            const int c = n0 + wn * 64 + q * 8 + col0;
            *(float2*)&C[(long long)r * ldc + c] =
                make_float2(acc[t][q][0] * s0, acc[t][q][1] * s0);
            *(float2*)&C[(long long)(r + 8) * ldc + c] =
                make_float2(acc[t][q][2] * s1, acc[t][q][3] * s1);
        }
    }
}

// ---------------------------------------------------------------------------
// fp16-acc GEMM body: 1 chain, A K-major, B MN-major (G2 specialization).
// ---------------------------------------------------------------------------
__device__ __forceinline__ void gemm_body_h(
    const __half* pA, const __half* pB,
    float* C, int K, int lda, int ldb, int ldc,
    int m0, int n0,
    uint32_t sb, int tid, int wid, int lane)
{
    constexpr uint32_t STAGEB = 2 * OPQ;
    const int wm = wid >> 1, wn = wid & 1;
    const int NKT = K >> 5;

    uint32_t acc[2][8][2];
#pragma unroll
    for (int t = 0; t < 2; t++)
#pragma unroll
        for (int q = 0; q < 8; q++) { acc[t][q][0] = 0u; acc[t][q][1] = 0u; }

    auto load_stage = [&](int kt, int st) {
        uint32_t nb = sb + (uint32_t)st * STAGEB;
        int k0 = kt * 32;
        load_opK(pA, lda, m0, k0, nb, tid);
        load_opMN(pB, ldb, n0, k0, nb + OPQ, tid);
        cp_commit();
    };

    load_stage(0, 0);
    load_stage(1, 1);

    int st = 0;
    for (int kt = 0; kt < NKT; kt++) {
        cp_wait1();
        __syncthreads();
        if (kt + 2 < NKT) load_stage(kt + 2, (st + 2) % 3);

        const uint32_t tb = sb + (uint32_t)st * STAGEB;
        const uint32_t sA = tb, sB = tb + OPQ;
#pragma unroll
        for (int ks = 0; ks < 2; ks++) {
            uint32_t a[2][4];
#pragma unroll
            for (int t = 0; t < 2; t++) {
                uint32_t off = (uint32_t)((wm * 32 + t * 16 + (lane & 15)) * 64
                                          + ks * 32 + (lane >> 4) * 16);
                ldsm4(a[t], sA + swzK(off));
            }
#pragma unroll
            for (int p = 0; p < 4; p++) {
                uint32_t bfr[4];
                uint32_t off = (uint32_t)((ks * 16 + (lane & 15)) * 256
                                          + (wn * 64 + p * 16 + (lane >> 4) * 8) * 2);
                ldsm4t(bfr, sB + swzMN(off));
#pragma unroll
                for (int t = 0; t < 2; t++)
#pragma unroll
                    for (int qq = 0; qq < 2; qq++) {
                        const int q = p * 2 + qq, h = qq * 2;
                        mma_f16h(acc[t][q], a[t], bfr[h], bfr[h + 1]);
                    }
            }
        }
        st = (st + 1) % 3;
    }

    const int row0 = lane >> 2, col0 = (lane & 3) * 2;
#pragma unroll
    for (int t = 0; t < 2; t++) {
        const int r = m0 + wm * 32 + t * 16 + row0;
#pragma unroll
        for (int q = 0; q < 8; q++) {
            const int c = n0 + wn * 64 + q * 8 + col0;
            float2 f0 = __half22float2(*(__half2*)&acc[t][q][0]);
            float2 f1 = __half22float2(*(__half2*)&acc[t][q][1]);
            *(float2*)&C[(long long)r * ldc + c] = f0;
            *(float2*)&C[(long long)(r + 8) * ldc + c] = f1;
        }
    }
}

// ---------------------------------------------------------------------------
// Softmax block body (identical math to R15).
// ---------------------------------------------------------------------------
__device__ __forceinline__ void softmax_block(
    int inner, int b,
    const float* __restrict__ S, __half* __restrict__ P,
    __half* __restrict__ QH, __half* __restrict__ QL, float* __restrict__ scQ,
    const float* __restrict__ pmask, const float* __restrict__ hmask,
    void* smemraw, int tid)
{
    float (*shm)[8][32] = (float(*)[8][32])smemraw;

    if (inner < LA) {
        const int i = inner;
        const long long rowoff = ((long long)b * LA + i) * LB;

        float4 s = *(const float4*)&S[rowoff + tid * 4];
        float4 h = *(const float4*)&hmask[(long long)b * LB + tid * 4];
        float l0 = s.x * h.x, l1 = s.y * h.y, l2 = s.z * h.z, l3 = s.w * h.w;

        float v = fmaxf(fmaxf(l0, l1), fmaxf(l2, l3));
#pragma unroll
        for (int o = 16; o; o >>= 1) v = fmaxf(v, __shfl_xor_sync(0xffffffffu, v, o));
        if ((tid & 31) == 0) shm[0][0][tid >> 5] = v;
        __syncthreads();
        float m = shm[0][0][0];
#pragma unroll
        for (int w = 1; w < 8; w++) m = fmaxf(m, shm[0][0][w]);
        __syncthreads();

        float e0 = __expf(l0 - m), e1 = __expf(l1 - m), e2 = __expf(l2 - m), e3 = __expf(l3 - m);
        float d = e0 + e1 + e2 + e3;
        float e = h.x * e0 + h.y * e1 + h.z * e2 + h.w * e3;
#pragma unroll
        for (int o = 16; o; o >>= 1) {
            d += __shfl_xor_sync(0xffffffffu, d, o);
            e += __shfl_xor_sync(0xffffffffu, e, o);
        }
        if ((tid & 31) == 0) { shm[0][0][tid >> 5] = d; shm[0][1][tid >> 5] = e; }
        __syncthreads();
        float D = 0.f, E = 0.f;
#pragma unroll
        for (int w = 0; w < 8; w++) { D += shm[0][0][w]; E += shm[0][1][w]; }

        const float pm = pmask[(long long)b * LA + i];
        const float scale = pm / (E + EPSV * D);

        __half2 o01 = __floats2half2_rn(h.x * e0 * scale, h.y * e1 * scale);
        __half2 o23 = __floats2half2_rn(h.z * e2 * scale, h.w * e3 * scale);
        *(uint2*)&P[rowoff + tid * 4] = make_uint2(*(uint32_t*)&o01, *(uint32_t*)&o23);
    } else {
        const int tx = tid & 31, ty = tid >> 5;
        const int j = (inner - LA) * 32 + tx;
        const float* Sb = S + (long long)b * LA * LB;
        __half* Qh = QH + (long long)b * LA * LB;
        __half* Ql = QL + (long long)b * LA * LB;
        const float* pm = pmask + (long long)b * LA;

        float m = -1e30f;
        for (int r = ty; r < LA; r += 8)
            m = fmaxf(m, Sb[(long long)r * LB + j] * pm[r]);
        shm[0][ty][tx] = m;
        __syncthreads();
        float M = shm[0][0][tx];
#pragma unroll
        for (int t = 1; t < 8; t++) M = fmaxf(M, shm[0][t][tx]);

        float D = 0.f, E = 0.f;
        for (int r = ty; r < LA; r += 8) {
            float pmr = pm[r];
            float ev = __expf(Sb[(long long)r * LB + j] * pmr - M);
            D += ev;
            float u = pmr * ev;
            E += u;
            __half hh = __float2half_rn(u);
            Qh[(long long)r * LB + j] = hh;
            Ql[(long long)r * LB + j] = __float2half_rn(u - __half2float(hh));
        }
        shm[1][ty][tx] = D; shm[2][ty][tx] = E;
        __syncthreads();
        float Dt = 0.f, Et = 0.f;
#pragma unroll
        for (int t = 0; t < 8; t++) { Dt += shm[1][t][tx]; Et += shm[2][t][tx]; }

        if (ty == 0)
            scQ[(long long)b * LB + j] = hmask[(long long)b * LB + j] / (Et + EPSV * Dt);
    }
}

#define SMEM_MEGA (3 * 4 * OPQ)   // 96 KB -> 2 CTAs/SM

// ---------------------------------------------------------------------------
// Mega kernel: block-index-ordered software pipeline with gpu-scope
// acquire/release gating. Every consumer thread performs its own acquire.
// ---------------------------------------------------------------------------
__global__ void __launch_bounds__(256, 2)
mega_kernel(const __half* __restrict__ pmH, const __half* __restrict__ pmL,
            const __half* __restrict__ hyH, const __half* __restrict__ hyL,
            float* __restrict__ S, __half* __restrict__ P,
            __half* __restrict__ QH, __half* __restrict__ QL,
            float* __restrict__ scQ,
            const float* __restrict__ pmask, const float* __restrict__ hmask,
            float* __restrict__ AP, float* __restrict__ AH)
{
    extern __shared__ char smem[];
    const uint32_t sb = smem_u32(smem);
    const int tid = threadIdx.x, wid = tid >> 5, lane = tid & 31;
    const int bid = blockIdx.x;

    if (bid < N_G1) {
        // ---- phase 1: G1 ----
        const int b = bid >> 6, y = (bid >> 3) & 7, x = bid & 7;
        gemm_body<3>(pmH + (long long)b * (LA * HD), pmL + (long long)b * (LA * HD),
                     hyH + (long long)b * (LB * HD), hyL + (long long)b * (LB * HD),
                     S + (long long)b * (LA * LB),
                     HD, HD, HD, LB,
                     y * 128, x * 128, 0, 0, nullptr, sb, tid, wid, lane);
        __threadfence();
        __syncthreads();
        if (tid == 0) red_release_add1(&g_cnt1[b]);
    } else if (bid < N_G1 + N_SM) {
        // ---- phase 2: softmax ----
        const int sid = bid - N_G1;
        const int b = sid / SM_PER_B, inner = sid % SM_PER_B;
        while (ld_acquire(&g_cnt1[b]) < 64) __nanosleep(256);
        __syncthreads();
        softmax_block(inner, b, S, P, QH, QL, scQ, pmask, hmask, smem, tid);
        __threadfence();
        __syncthreads();
        if (tid == 0) red_release_add1(&g_cnt2[b]);
    } else {
        // ---- phase 3: G23 ----
        const int gid = bid - N_G1 - N_SM;
        const int x = gid & 3, y = (gid >> 2) & 7, z = gid >> 5;
        const int b = (z < NB) ? z : z - NB;
        while (ld_acquire(&g_cnt2[b]) < SM_PER_B) __nanosleep(256);
        __syncthreads();
        if (z < NB) {
            gemm_body_h(P + (long long)b * (LA * LB),
                        hyH + (long long)b * (LB * HD),
                        AP + (long long)b * (LA * HD),
                        LB, LB, HD, HD,
                        y * 128, x * 128, sb, tid, wid, lane);
        } else {
            gemm_body<3>(QH + (long long)b * (LA * LB), QL + (long long)b * (LA * LB),
                         pmH + (long long)b * (LA * HD), pmL + (long long)b * (LA * HD),
                         AH + (long long)b * (LB * HD),
                         LA, LB, HD, HD,
                         y * 128, x * 128, 1, 1,
                         scQ + (long long)b * LB, sb, tid, wid, lane);
        }
    }
}

// ---------------------------------------------------------------------------
extern "C" void kernel_launch(void* const* d_in, const int* in_sizes, int n_in,
                              void* d_out, int out_size)
{
    const float* prem  = (const float*)d_in[0];
    const float* pmask = (const float*)d_in[1];
    const float* hyp   = (const float*)d_in[2];
    const float* hmask = (const float*)d_in[3];

    float* AP  = (float*)d_out;
    float* AHo = AP + (long long)NB * LA * HD;

    void *pS, *pP, *pQH, *pQL, *pscQ, *ppmH, *ppmL, *phyH, *phyL, *pc1, *pc2;
    cudaGetSymbolAddress(&pS, g_S);
    cudaGetSymbolAddress(&pP, g_P);
    cudaGetSymbolAddress(&pQH, g_QH); cudaGetSymbolAddress(&pQL, g_QL);
    cudaGetSymbolAddress(&pscQ, g_scQ);
    cudaGetSymbolAddress(&ppmH, g_pmH); cudaGetSymbolAddress(&ppmL, g_pmL);
    cudaGetSymbolAddress(&phyH, g_hyH); cudaGetSymbolAddress(&phyL, g_hyL);
    cudaGetSymbolAddress(&pc1, g_cnt1); cudaGetSymbolAddress(&pc2, g_cnt2);
    float* S = (float*)pS;
    __half *P = (__half*)pP;
    __half *QH = (__half*)pQH, *QL = (__half*)pQL;
    float* scQ = (float*)pscQ;
    __half *pmH = (__half*)ppmH, *pmL = (__half*)ppmL;
    __half *hyH = (__half*)phyH, *hyL = (__half*)phyL;

    cudaFuncSetAttribute(mega_kernel, cudaFuncAttributeMaxDynamicSharedMemorySize, SMEM_MEGA);

    // 0) zero pipeline counters (every launch / graph replay)
    cudaMemsetAsync(pc1, 0, NB * sizeof(int));
    cudaMemsetAsync(pc2, 0, NB * sizeof(int));

    // 1) split inputs into fp16 hi/lo
    {
        int nblk = (int)((long long)NB * LA * HD / 1024);
        split_kernel<<<nblk, 256>>>(prem, pmH, pmL);
        split_kernel<<<nblk, 256>>>(hyp, hyH, hyL);
    }
    // 2) pipelined G1 -> softmax -> G23 in one launch
    {
        mega_kernel<<<N_G1 + N_SM + N_G23, 256, SMEM_MEGA>>>(
            pmH, pmL, hyH, hyL, S, P, QH, QL, scQ, pmask, hmask, AP, AHo);
    }
}